// round 14
// baseline (speedup 1.0000x reference)
#include <cuda_runtime.h>
#include <cuda_bf16.h>
#include <cstdint>

#define B_ROWS 4096
#define M_ROWS 12893
#define M_PAD  13056          // 51 * 256
#define D_DIM  2048

#define BM 128                // CTA rows
#define BN 256                // CTA cols
#define BK 64                 // k-chunk: 64 bf16 = 128B = one swizzle row
#define NK (D_DIM / BK)       // 32
#define STAGES 3
#define A_BYTES (BM * 128)    // 16384
#define B_BYTES (BN * 128)    // 32768
#define B_OFF_S A_BYTES
#define STAGE_BYTES (A_BYTES + B_BYTES)       // 49152
#define SMEM_DYN (STAGES * STAGE_BYTES)       // 147456; holds 128x257 f32 epilogue too

// ---------------- device scratch (allocation-free rule) ----------------
__device__ __nv_bfloat16 g_xn[(size_t)B_ROWS * D_DIM];
__device__ __nv_bfloat16 g_pn[(size_t)M_PAD * D_DIM];
__device__ float g_xs[B_ROWS];
__device__ float g_ps[M_PAD];

__device__ __forceinline__ void cp_async16(uint32_t sa, const void* gp) {
    asm volatile("cp.async.cg.shared.global [%0], [%1], 16;" :: "r"(sa), "l"(gp));
}
__device__ __forceinline__ void ldsm_x4(uint32_t& r0, uint32_t& r1,
                                        uint32_t& r2, uint32_t& r3, uint32_t a) {
    asm volatile("ldmatrix.sync.aligned.m8n8.x4.shared.b16 {%0,%1,%2,%3}, [%4];"
                 : "=r"(r0), "=r"(r1), "=r"(r2), "=r"(r3) : "r"(a));
}

// ---------------- normalize (x and prototypes fused in one grid) ----------------
__device__ __forceinline__ float block_reduce_sum(float v, float* red) {
    #pragma unroll
    for (int o = 16; o > 0; o >>= 1) v += __shfl_xor_sync(0xffffffffu, v, o);
    int w = threadIdx.x >> 5;
    if ((threadIdx.x & 31) == 0) red[w] = v;
    __syncthreads();
    if (threadIdx.x < 32) {
        float t = (threadIdx.x < 8) ? red[threadIdx.x] : 0.f;
        #pragma unroll
        for (int o = 4; o > 0; o >>= 1) t += __shfl_xor_sync(0xffffffffu, t, o);
        if (threadIdx.x == 0) red[0] = t;
    }
    __syncthreads();
    float r = red[0];
    __syncthreads();
    return r;
}

__global__ void __launch_bounds__(256) normalize_all(const float* __restrict__ x,
                                                     const float* __restrict__ pr) {
    __shared__ float red[8];
    const int tid = threadIdx.x;
    int row;
    const float* in;
    __nv_bfloat16* out;
    float* sq;
    if (blockIdx.x < B_ROWS) {
        row = blockIdx.x;
        in = x; out = g_xn; sq = g_xs;
    } else {
        row = blockIdx.x - B_ROWS;
        in = pr; out = g_pn; sq = g_ps;
        if (row >= M_ROWS) {
            __nv_bfloat16 z = __float2bfloat16(0.f);
            for (int i = tid; i < D_DIM; i += 256) out[(size_t)row * D_DIM + i] = z;
            if (tid == 0) sq[row] = 0.f;
            return;
        }
    }
    const float4* rp = (const float4*)(in + (size_t)row * D_DIM);
    float4 v0 = rp[tid];
    float4 v1 = rp[tid + 256];
    float s = v0.x * v0.x + v0.y * v0.y + v0.z * v0.z + v0.w * v0.w
            + v1.x * v1.x + v1.y * v1.y + v1.z * v1.z + v1.w * v1.w;
    float tot = block_reduce_sum(s, red);
    float inv = 1.f / fmaxf(sqrtf(tot), 1e-12f);

    float n0x = v0.x * inv, n0y = v0.y * inv, n0z = v0.z * inv, n0w = v0.w * inv;
    float n1x = v1.x * inv, n1y = v1.y * inv, n1z = v1.z * inv, n1w = v1.w * inv;
    float ss = n0x * n0x + n0y * n0y + n0z * n0z + n0w * n0w
             + n1x * n1x + n1y * n1y + n1z * n1z + n1w * n1w;

    __nv_bfloat162* o2 = (__nv_bfloat162*)(out + (size_t)row * D_DIM);
    int b0 = tid * 2, b1 = 512 + tid * 2;
    o2[b0]     = __floats2bfloat162_rn(n0x, n0y);
    o2[b0 + 1] = __floats2bfloat162_rn(n0z, n0w);
    o2[b1]     = __floats2bfloat162_rn(n1x, n1y);
    o2[b1 + 1] = __floats2bfloat162_rn(n1z, n1w);

    float stot = block_reduce_sum(ss, red);
    if (tid == 0) sq[row] = stot;
}

// ---- bf16 mma.sync GEMM: R4 mainloop verbatim, coalesced smem epilogue ----
__global__ void __launch_bounds__(512, 1) gemm_dist_mma(const float* __restrict__ dscale,
                                                        float* __restrict__ out) {
    extern __shared__ __align__(1024) char smem[];
    const uint32_t sbase = (uint32_t)__cvta_generic_to_shared(smem);

    const int tid  = threadIdx.x;
    const int lane = tid & 31;
    const int warp = tid >> 5;
    const int wm = warp >> 2;      // 0..3: 32-row strip
    const int wn = warp & 3;       // 0..3: 64-col strip
    const int bm0 = blockIdx.y * BM;
    const int bn  = blockIdx.x * BN;

    // ldmatrix lane addressing (SW128: swz(r*128+cb) = r*128 + (cb ^ ((r&7)*16)))
    const int a_row = (lane & 7) + ((lane >> 3) & 1) * 8;
    const int a_kh  = lane >> 4;
    const int b_row = (lane & 7) + (lane >> 4) * 8;
    const int b_kh  = (lane >> 3) & 1;
    const uint32_t xm = (lane & 7) * 16;

    uint32_t aoff[2], boff[4];
    #pragma unroll
    for (int i = 0; i < 2; i++) aoff[i] = (wm * 32 + i * 16 + a_row) * 128;
    #pragma unroll
    for (int jb = 0; jb < 4; jb++)
        boff[jb] = B_OFF_S + (wn * 64 + jb * 16 + b_row) * 128;

    float acc[2][8][4];
    #pragma unroll
    for (int i = 0; i < 2; i++)
        #pragma unroll
        for (int j = 0; j < 8; j++)
            #pragma unroll
            for (int t = 0; t < 4; t++) acc[i][j][t] = 0.f;

    auto loadStage = [&](int st, int kt) {
        const int k0 = kt * BK;
        const uint32_t base = sbase + st * STAGE_BYTES;
        #pragma unroll
        for (int h = 0; h < 2; h++) {               // A: 1024 16B chunks
            int c = tid + h * 512;
            int row = c >> 3, q = c & 7;
            cp_async16(base + row * 128 + ((q * 16) ^ ((row & 7) * 16)),
                       g_xn + (size_t)(bm0 + row) * D_DIM + k0 + q * 8);
        }
        #pragma unroll
        for (int h = 0; h < 4; h++) {               // B: 2048 16B chunks
            int c = tid + h * 512;
            int row = c >> 3, q = c & 7;
            cp_async16(base + B_OFF_S + row * 128 + ((q * 16) ^ ((row & 7) * 16)),
                       g_pn + (size_t)(bn + row) * D_DIM + k0 + q * 8);
        }
    };

    loadStage(0, 0);
    asm volatile("cp.async.commit_group;" ::: "memory");
    loadStage(1, 1);
    asm volatile("cp.async.commit_group;" ::: "memory");

    for (int kt = 0; kt < NK; kt++) {
        asm volatile("cp.async.wait_group 1;" ::: "memory");
        __syncthreads();

        if (kt + 2 < NK) loadStage((kt + 2) % STAGES, kt + 2);
        asm volatile("cp.async.commit_group;" ::: "memory");

        const uint32_t base = sbase + (kt % STAGES) * STAGE_BYTES;
        #pragma unroll
        for (int ks = 0; ks < 4; ks++) {
            const uint32_t ca = ((uint32_t)(ks * 32 + a_kh * 16)) ^ xm;
            const uint32_t cb = ((uint32_t)(ks * 32 + b_kh * 16)) ^ xm;
            uint32_t A[2][4];
            #pragma unroll
            for (int i = 0; i < 2; i++)
                ldsm_x4(A[i][0], A[i][1], A[i][2], A[i][3], base + aoff[i] + ca);
            uint32_t Bf[8][2];
            #pragma unroll
            for (int jb = 0; jb < 4; jb++) {
                uint32_t r0, r1, r2, r3;
                ldsm_x4(r0, r1, r2, r3, base + boff[jb] + cb);
                Bf[2 * jb][0] = r0; Bf[2 * jb][1] = r1;
                Bf[2 * jb + 1][0] = r2; Bf[2 * jb + 1][1] = r3;
            }
            #pragma unroll
            for (int i = 0; i < 2; i++)
                #pragma unroll
                for (int j = 0; j < 8; j++) {
                    asm volatile(
                        "mma.sync.aligned.m16n8k16.row.col.f32.bf16.bf16.f32 "
                        "{%0,%1,%2,%3}, {%4,%5,%6,%7}, {%8,%9}, {%0,%1,%2,%3};"
                        : "+f"(acc[i][j][0]), "+f"(acc[i][j][1]),
                          "+f"(acc[i][j][2]), "+f"(acc[i][j][3])
                        : "r"(A[i][0]), "r"(A[i][1]), "r"(A[i][2]), "r"(A[i][3]),
                          "r"(Bf[j][0]), "r"(Bf[j][1]));
                }
        }
    }

    // ---- fused epilogue: dist -> smem tile -> fully coalesced stores
    const float absS = fabsf(dscale[0]);
    float* sT = (float*)smem;                     // 128 x 257 f32
    __syncthreads();
    #pragma unroll
    for (int i = 0; i < 2; i++) {
        const int rl = wm * 32 + i * 16 + (lane >> 2);
        const float xs0 = g_xs[bm0 + rl];
        const float xs1 = g_xs[bm0 + rl + 8];
        #pragma unroll
        for (int j = 0; j < 8; j++) {
            const int cl = wn * 64 + j * 8 + (lane & 3) * 2;
            const float ps0 = __ldg(&g_ps[bn + cl]);
            const float ps1 = __ldg(&g_ps[bn + cl + 1]);
            sT[rl * 257 + cl]           = -absS * sqrtf(fmaxf(xs0 + ps0 - 2.f * acc[i][j][0], 0.f));
            sT[rl * 257 + cl + 1]       = -absS * sqrtf(fmaxf(xs0 + ps1 - 2.f * acc[i][j][1], 0.f));
            sT[(rl + 8) * 257 + cl]     = -absS * sqrtf(fmaxf(xs1 + ps0 - 2.f * acc[i][j][2], 0.f));
            sT[(rl + 8) * 257 + cl + 1] = -absS * sqrtf(fmaxf(xs1 + ps1 - 2.f * acc[i][j][3], 0.f));
        }
    }
    __syncthreads();
    const int col = tid & 255;
    const int rh  = tid >> 8;          // 2 rows per iteration
    const bool ok = (bn + col < M_ROWS);
    for (int r2 = 0; r2 < 64; r2++) {
        const int r = r2 * 2 + rh;
        if (ok) out[(size_t)(bm0 + r) * M_ROWS + bn + col] = sT[r * 257 + col];
    }
}

extern "C" void kernel_launch(void* const* d_in, const int* in_sizes, int n_in,
                              void* d_out, int out_size) {
    const float* x  = (const float*)d_in[0];   // [4096, 2048]
    const float* pr = (const float*)d_in[1];   // [12893, 2048]
    const float* sc = (const float*)d_in[2];   // [1]
    float* out = (float*)d_out;                // [4096, 12893]

    cudaFuncSetAttribute(gemm_dist_mma,
                         cudaFuncAttributeMaxDynamicSharedMemorySize, SMEM_DYN);

    normalize_all<<<B_ROWS + M_PAD, 256>>>(x, pr);

    dim3 grid(M_PAD / BN, B_ROWS / BM);        // 51 x 32
    gemm_dist_mma<<<grid, 512, SMEM_DYN>>>(sc, out);
}

// round 15
// speedup vs baseline: 1.2047x; 1.2047x over previous
#include <cuda_runtime.h>
#include <cuda_bf16.h>
#include <cstdint>

#define B_ROWS 4096
#define M_ROWS 12893
#define M_PAD  13056          // 51 * 256
#define D_DIM  2048

#define BM 128                // CTA rows
#define BN 256                // CTA cols
#define BK 64                 // k-chunk: 64 bf16 = 128B = one swizzle row
#define NK (D_DIM / BK)       // 32
#define STAGES 3
#define A_BYTES (BM * 128)    // 16384
#define B_BYTES (BN * 128)    // 32768
#define B_OFF_S A_BYTES
#define STAGE_BYTES (A_BYTES + B_BYTES)       // 49152
#define SMEM_DYN (STAGES * STAGE_BYTES)       // 147456

// ---------------- device scratch (allocation-free rule) ----------------
__device__ __nv_bfloat16 g_xn[(size_t)B_ROWS * D_DIM];
__device__ __nv_bfloat16 g_pn[(size_t)M_PAD * D_DIM];
__device__ float g_xs[B_ROWS];
__device__ float g_ps[M_PAD];

__device__ __forceinline__ void cp_async16(uint32_t sa, const void* gp) {
    asm volatile("cp.async.cg.shared.global [%0], [%1], 16;" :: "r"(sa), "l"(gp));
}
__device__ __forceinline__ void ldsm_x4(uint32_t& r0, uint32_t& r1,
                                        uint32_t& r2, uint32_t& r3, uint32_t a) {
    asm volatile("ldmatrix.sync.aligned.m8n8.x4.shared.b16 {%0,%1,%2,%3}, [%4];"
                 : "=r"(r0), "=r"(r1), "=r"(r2), "=r"(r3) : "r"(a));
}

// ---------------- normalize (x and prototypes fused in one grid) ----------------
__device__ __forceinline__ float block_reduce_sum(float v, float* red) {
    #pragma unroll
    for (int o = 16; o > 0; o >>= 1) v += __shfl_xor_sync(0xffffffffu, v, o);
    int w = threadIdx.x >> 5;
    if ((threadIdx.x & 31) == 0) red[w] = v;
    __syncthreads();
    if (threadIdx.x < 32) {
        float t = (threadIdx.x < 8) ? red[threadIdx.x] : 0.f;
        #pragma unroll
        for (int o = 4; o > 0; o >>= 1) t += __shfl_xor_sync(0xffffffffu, t, o);
        if (threadIdx.x == 0) red[0] = t;
    }
    __syncthreads();
    float r = red[0];
    __syncthreads();
    return r;
}

__global__ void __launch_bounds__(256) normalize_all(const float* __restrict__ x,
                                                     const float* __restrict__ pr) {
    __shared__ float red[8];
    const int tid = threadIdx.x;
    int row;
    const float* in;
    __nv_bfloat16* out;
    float* sq;
    if (blockIdx.x < B_ROWS) {
        row = blockIdx.x;
        in = x; out = g_xn; sq = g_xs;
    } else {
        row = blockIdx.x - B_ROWS;
        in = pr; out = g_pn; sq = g_ps;
        if (row >= M_ROWS) {
            __nv_bfloat16 z = __float2bfloat16(0.f);
            for (int i = tid; i < D_DIM; i += 256) out[(size_t)row * D_DIM + i] = z;
            if (tid == 0) sq[row] = 0.f;
            return;
        }
    }
    const float4* rp = (const float4*)(in + (size_t)row * D_DIM);
    float4 v0 = rp[tid];
    float4 v1 = rp[tid + 256];
    float s = v0.x * v0.x + v0.y * v0.y + v0.z * v0.z + v0.w * v0.w
            + v1.x * v1.x + v1.y * v1.y + v1.z * v1.z + v1.w * v1.w;
    float tot = block_reduce_sum(s, red);
    float inv = 1.f / fmaxf(sqrtf(tot), 1e-12f);

    float n0x = v0.x * inv, n0y = v0.y * inv, n0z = v0.z * inv, n0w = v0.w * inv;
    float n1x = v1.x * inv, n1y = v1.y * inv, n1z = v1.z * inv, n1w = v1.w * inv;
    float ss = n0x * n0x + n0y * n0y + n0z * n0z + n0w * n0w
             + n1x * n1x + n1y * n1y + n1z * n1z + n1w * n1w;

    __nv_bfloat162* o2 = (__nv_bfloat162*)(out + (size_t)row * D_DIM);
    int b0 = tid * 2, b1 = 512 + tid * 2;
    o2[b0]     = __floats2bfloat162_rn(n0x, n0y);
    o2[b0 + 1] = __floats2bfloat162_rn(n0z, n0w);
    o2[b1]     = __floats2bfloat162_rn(n1x, n1y);
    o2[b1 + 1] = __floats2bfloat162_rn(n1z, n1w);

    float stot = block_reduce_sum(ss, red);
    if (tid == 0) sq[row] = stot;
}

// ---------------- mma.sync GEMM + fused distance epilogue (R4 verbatim) --------
__global__ void __launch_bounds__(512, 1) gemm_dist_mma(const float* __restrict__ dscale,
                                                        float* __restrict__ out) {
    extern __shared__ __align__(1024) char smem[];
    const uint32_t sbase = (uint32_t)__cvta_generic_to_shared(smem);

    const int tid  = threadIdx.x;
    const int lane = tid & 31;
    const int warp = tid >> 5;
    const int wm = warp >> 2;      // 0..3: 32-row strip
    const int wn = warp & 3;       // 0..3: 64-col strip
    const int bm0 = blockIdx.y * BM;
    const int bn  = blockIdx.x * BN;

    // ---- ldmatrix lane address precompute (SW128: swz(r*128+cb)=r*128+(cb^((r&7)*16)))
    const int a_row = (lane & 7) + ((lane >> 3) & 1) * 8;  // 0..15
    const int a_kh  = lane >> 4;                            // k half
    const int b_row = (lane & 7) + (lane >> 4) * 8;         // n local 0..15
    const int b_kh  = (lane >> 3) & 1;
    const uint32_t xm = (lane & 7) * 16;

    uint32_t aoff[2], boff[4];
    #pragma unroll
    for (int i = 0; i < 2; i++) aoff[i] = (wm * 32 + i * 16 + a_row) * 128;
    #pragma unroll
    for (int jb = 0; jb < 4; jb++)
        boff[jb] = B_OFF_S + (wn * 64 + jb * 16 + b_row) * 128;

    float acc[2][8][4];
    #pragma unroll
    for (int i = 0; i < 2; i++)
        #pragma unroll
        for (int j = 0; j < 8; j++)
            #pragma unroll
            for (int t = 0; t < 4; t++) acc[i][j][t] = 0.f;

    auto loadStage = [&](int st, int kt) {
        const int k0 = kt * BK;
        const uint32_t base = sbase + st * STAGE_BYTES;
        #pragma unroll
        for (int h = 0; h < 2; h++) {               // A: 1024 16B chunks
            int c = tid + h * 512;
            int row = c >> 3, q = c & 7;
            cp_async16(base + row * 128 + ((q * 16) ^ ((row & 7) * 16)),
                       g_xn + (size_t)(bm0 + row) * D_DIM + k0 + q * 8);
        }
        #pragma unroll
        for (int h = 0; h < 4; h++) {               // B: 2048 16B chunks
            int c = tid + h * 512;
            int row = c >> 3, q = c & 7;
            cp_async16(base + B_OFF_S + row * 128 + ((q * 16) ^ ((row & 7) * 16)),
                       g_pn + (size_t)(bn + row) * D_DIM + k0 + q * 8);
        }
    };

    loadStage(0, 0);
    asm volatile("cp.async.commit_group;" ::: "memory");
    loadStage(1, 1);
    asm volatile("cp.async.commit_group;" ::: "memory");

    for (int kt = 0; kt < NK; kt++) {
        asm volatile("cp.async.wait_group 1;" ::: "memory");
        __syncthreads();

        if (kt + 2 < NK) loadStage((kt + 2) % STAGES, kt + 2);
        asm volatile("cp.async.commit_group;" ::: "memory");

        const uint32_t base = sbase + (kt % STAGES) * STAGE_BYTES;
        #pragma unroll
        for (int ks = 0; ks < 4; ks++) {
            const uint32_t ca = ((uint32_t)(ks * 32 + a_kh * 16)) ^ xm;
            const uint32_t cb = ((uint32_t)(ks * 32 + b_kh * 16)) ^ xm;
            uint32_t A[2][4];
            #pragma unroll
            for (int i = 0; i < 2; i++)
                ldsm_x4(A[i][0], A[i][1], A[i][2], A[i][3], base + aoff[i] + ca);
            uint32_t Bf[8][2];
            #pragma unroll
            for (int jb = 0; jb < 4; jb++) {
                uint32_t r0, r1, r2, r3;
                ldsm_x4(r0, r1, r2, r3, base + boff[jb] + cb);
                Bf[2 * jb][0] = r0; Bf[2 * jb][1] = r1;
                Bf[2 * jb + 1][0] = r2; Bf[2 * jb + 1][1] = r3;
            }
            #pragma unroll
            for (int i = 0; i < 2; i++)
                #pragma unroll
                for (int j = 0; j < 8; j++) {
                    asm volatile(
                        "mma.sync.aligned.m16n8k16.row.col.f32.bf16.bf16.f32 "
                        "{%0,%1,%2,%3}, {%4,%5,%6,%7}, {%8,%9}, {%0,%1,%2,%3};"
                        : "+f"(acc[i][j][0]), "+f"(acc[i][j][1]),
                          "+f"(acc[i][j][2]), "+f"(acc[i][j][3])
                        : "r"(A[i][0]), "r"(A[i][1]), "r"(A[i][2]), "r"(A[i][3]),
                          "r"(Bf[j][0]), "r"(Bf[j][1]));
                }
        }
    }

    // ---- fused epilogue: -|s| * sqrt(max(xs + ps - 2*acc, 0))
    const float absS = fabsf(dscale[0]);
    #pragma unroll
    for (int i = 0; i < 2; i++) {
        const int r = bm0 + wm * 32 + i * 16 + (lane >> 2);
        const float xs0 = g_xs[r];
        const float xs1 = g_xs[r + 8];
        #pragma unroll
        for (int j = 0; j < 8; j++) {
            const int c = bn + wn * 64 + j * 8 + (lane & 3) * 2;
            const float ps0 = __ldg(&g_ps[c]);
            const float ps1 = __ldg(&g_ps[c + 1]);
            float v00 = -absS * sqrtf(fmaxf(xs0 + ps0 - 2.f * acc[i][j][0], 0.f));
            float v01 = -absS * sqrtf(fmaxf(xs0 + ps1 - 2.f * acc[i][j][1], 0.f));
            float v10 = -absS * sqrtf(fmaxf(xs1 + ps0 - 2.f * acc[i][j][2], 0.f));
            float v11 = -absS * sqrtf(fmaxf(xs1 + ps1 - 2.f * acc[i][j][3], 0.f));
            if (c + 1 < M_ROWS) {
                out[(size_t)r * M_ROWS + c] = v00;
                out[(size_t)r * M_ROWS + c + 1] = v01;
                out[(size_t)(r + 8) * M_ROWS + c] = v10;
                out[(size_t)(r + 8) * M_ROWS + c + 1] = v11;
            } else if (c < M_ROWS) {
                out[(size_t)r * M_ROWS + c] = v00;
                out[(size_t)(r + 8) * M_ROWS + c] = v10;
            }
        }
    }
}

extern "C" void kernel_launch(void* const* d_in, const int* in_sizes, int n_in,
                              void* d_out, int out_size) {
    const float* x  = (const float*)d_in[0];   // [4096, 2048]
    const float* pr = (const float*)d_in[1];   // [12893, 2048]
    const float* sc = (const float*)d_in[2];   // [1]
    float* out = (float*)d_out;                // [4096, 12893]

    cudaFuncSetAttribute(gemm_dist_mma,
                         cudaFuncAttributeMaxDynamicSharedMemorySize, SMEM_DYN);

    normalize_all<<<B_ROWS + M_PAD, 256>>>(x, pr);

    dim3 grid(M_PAD / BN, B_ROWS / BM);        // 51 x 32
    gemm_dist_mma<<<grid, 512, SMEM_DYN>>>(sc, out);
}